// round 17
// baseline (speedup 1.0000x reference)
#include <cuda_runtime.h>

#define NCLS  19
#define DIM   256
#define NPIX  4096
#define NBINS 51
#define NW    (NCLS * DIM)    // 4864 tasks; 1 per warp
#define NBLK  (NW / 2)        // 2432 blocks x 2 warps; 17 blocks/SM -> 1 wave

// ---- scratch (no allocations allowed) ----
__device__ int   g_off[NCLS + 1];
__device__ int   g_cnt[NCLS];
__device__ float g_Fs[DIM * NPIX];          // class-sorted values, d-major
__device__ float g_clsum2[NCLS * 32];       // spread class partial sums
__device__ int   g_ticket;

__device__ __forceinline__ float wredsum(float v) {
#pragma unroll
    for (int m = 16; m; m >>= 1) v += __shfl_xor_sync(0xffffffffu, v, m);
    return v;
}

__device__ __forceinline__ float ex2(float x) {
    float e;
    asm("ex2.approx.ftz.f32 %0, %1;" : "=f"(e) : "f"(x));
    return e;
}

// Packed f32x2 helpers (Blackwell sm_103a; only reachable via PTX).
__device__ __forceinline__ unsigned long long pk2(float lo, float hi) {
    unsigned long long r;
    asm("mov.b64 %0, {%1, %2};" : "=l"(r) : "f"(lo), "f"(hi));
    return r;
}
__device__ __forceinline__ void upk2(unsigned long long v, float& lo, float& hi) {
    asm("mov.b64 {%0, %1}, %2;" : "=f"(lo), "=f"(hi) : "l"(v));
}
#define ADD2(d, a, b) asm("add.rn.f32x2 %0, %1, %2;" : "=l"(d) : "l"(a), "l"(b))
#define MUL2(d, a, b) asm("mul.rn.f32x2 %0, %1, %2;" : "=l"(d) : "l"(a), "l"(b))

// Packed recurrence KDE: E2_{k+1} = E2_k*t2_k, t2_{k+1} = t2_k*sg2, with the
// two pixels of a pair in the two f32x2 halves -> 3 packed ops per bin.
// Anchored per 9/8-bin segment via scalar EX2; chain biased by 2^88.
// Valid for var >= 0.6 (caller guards).
template <int KB, int BSTART>
__device__ __forceinline__ void kde_recp(const float* __restrict__ vals, int cnt,
                                         int lane, float a_s,
                                         unsigned long long sg2,
                                         float* sh_out) {
    constexpr int S0 = (KB + 1) / 2;      // 17 -> 9
    unsigned long long acc2[KB];
#pragma unroll
    for (int k = 0; k < KB; k++) acc2[k] = 0ull;
    float as04  = 0.4f  * a_s;
    float as004 = 0.04f * a_s;
    int i = lane;
    for (; i + 32 < cnt; i += 64) {
        float fa = vals[i];
        float fb = vals[i + 32];
#pragma unroll
        for (int s = 0; s < 2; s++) {
            const int sb = s ? S0 : 0;
            const int L  = s ? (KB - S0) : S0;
            float bk = -5.f + 0.2f * (float)(BSTART + sb);
            float da = bk - fa, db = bk - fb;
            float Ea = ex2(fmaf(a_s * da, da, 88.f));            // biased
            float Eb = ex2(fmaf(a_s * db, db, 88.f));
            float ta = ex2(fminf(fmaf(as04, da, as004), 126.f)); // no inf
            float tb = ex2(fminf(fmaf(as04, db, as004), 126.f));
            unsigned long long E2 = pk2(Ea, Eb);
            unsigned long long t2 = pk2(ta, tb);
#pragma unroll
            for (int j = 0; j < L; j++) {
                ADD2(acc2[sb + j], acc2[sb + j], E2);
                MUL2(E2, E2, t2);
                MUL2(t2, t2, sg2);
            }
        }
    }
    if (i < cnt) {                        // <=1 single-pixel tail (biased too)
        float fa = vals[i];
        float p1 = (-2.f * a_s) * fa;
        float p0 = fmaf(a_s * fa, fa, 88.f);
#pragma unroll
        for (int k = 0; k < KB; k++) {
            float bk = -5.f + 0.2f * (float)(BSTART + k);
            float e = ex2(fmaf(a_s, bk * bk, fmaf(p1, bk, p0)));
            unsigned long long e2 = pk2(e, 0.f);
            ADD2(acc2[k], acc2[k], e2);
        }
    }
#pragma unroll
    for (int k = 0; k < KB; k++) {
        float lo, hi;
        upk2(acc2[k], lo, hi);
        float v = wredsum(lo + hi) * 3.2311742677852644e-27f;   // * 2^-88
        if (lane == 0) sh_out[k] = v;
    }
}

// Direct per-bin EX2 path (fallback for small var; always correct).
template <int KB, int BSTART>
__device__ __noinline__ void kde_direct(const float* __restrict__ vals, int cnt,
                                        int lane, float a_s, float* sh_out) {
    float acc[KB];
#pragma unroll
    for (int k = 0; k < KB; k++) acc[k] = 0.f;
    for (int i = lane; i < cnt; i += 32) {
        float fa = vals[i];
        float p1 = (-2.f * a_s) * fa, p0 = a_s * fa * fa;
#pragma unroll
        for (int k = 0; k < KB; k++) {
            float bk = -5.f + 0.2f * (float)(BSTART + k);
            acc[k] += ex2(fmaf(a_s, bk * bk, fmaf(p1, bk, p0)));
        }
    }
#pragma unroll
    for (int k = 0; k < KB; k++) {
        acc[k] = wredsum(acc[k]);
        if (lane == 0) sh_out[k] = acc[k];
    }
}

// K0: block handles dims d and d+128. Block-local counting sort (labels are
// 16KB, L2-broadcast) + gather into g_Fs.
__global__ void __launch_bounds__(256) k_gp(const int* __restrict__ lab32,
                                            const float* __restrict__ feature) {
    __shared__ short sperm[NPIX];          // 8KB
    __shared__ int scnt[8][20];            // [warp][class] -> excl prefix
    __shared__ int stot[20];
    __shared__ int soff[20];
    int tid  = threadIdx.x;
    int w    = tid >> 5;
    int lane = tid & 31;

    // words [0,4096): in-bounds under both dtype views of the label buffer.
    int aw[16];
#pragma unroll
    for (int r = 0; r < 16; r++) aw[r] = lab32[tid + r * 256];
    // int64 labels (0..18): all odd words zero; odd words owned by odd tid.
    int any = 0;
    if (tid & 1) {
#pragma unroll
        for (int r = 0; r < 16; r++) any |= aw[r];
    }
    int is32 = __syncthreads_or(any);

    if (lane < 20) scnt[w][lane] = 0;
    __syncwarp();

    int cs[16], rs[16];
#pragma unroll
    for (int r = 0; r < 16; r++) {
        int n = tid + r * 256;
        int c = is32 ? aw[r] : lab32[2 * n];
        c = max(0, min(NCLS - 1, c));
        cs[r] = c;
        unsigned mask = __match_any_sync(0xffffffffu, c);
        int base = scnt[w][c];
        rs[r] = base + __popc(mask & ((1u << lane) - 1u));
        if (lane == (__ffs(mask) - 1)) scnt[w][c] = base + __popc(mask);
        __syncwarp();
    }
    __syncthreads();

    // cross-warp exclusive prefix per class
    if (tid < NCLS) {
        int run = 0;
#pragma unroll
        for (int w2 = 0; w2 < 8; w2++) {
            int t = scnt[w2][tid];
            scnt[w2][tid] = run;
            run += t;
        }
        stot[tid] = run;
    }
    __syncthreads();
    if (tid == 0) {
        int off = 0;
        for (int c = 0; c < NCLS; c++) { soff[c] = off; off += stot[c]; }
    }
    __syncthreads();

#pragma unroll
    for (int r = 0; r < 16; r++) {
        int c = cs[r];
        sperm[soff[c] + scnt[w][c] + rs[r]] = (short)(tid + r * 256);
    }

    if (blockIdx.x == 0) {
        if (tid < NCLS) { g_cnt[tid] = stot[tid]; g_off[tid] = soff[tid]; }
        if (tid == NCLS) g_off[NCLS] = NPIX;
        for (int i = tid; i < NCLS * 32; i += 256) g_clsum2[i] = 0.f;
        if (tid == 255) g_ticket = 0;
    }
    __syncthreads();

#pragma unroll 1
    for (int dd = 0; dd < 2; dd++) {
        int d = blockIdx.x + dd * 128;
        const float* __restrict__ src = feature + d * NPIX;
        float* __restrict__ dst = g_Fs + d * NPIX;
        for (int j = tid; j < NPIX; j += 256)
            dst[j] = src[sperm[j]];
    }
}

// K1: 64-thread blocks (2 warps), 17 blocks/SM -> 34 warps/SM, 1 wave,
// 60-reg budget. Stats pass + 3x17-bin packed-recurrence KDE + epilogue +
// spread atomic + ticketed finalize + overlapped output copy.
__global__ void __launch_bounds__(64, 17)
k_main(const float* __restrict__ feature, float* __restrict__ out, int nf) {
    __shared__ float sh[2][52];
    int wslot = threadIdx.x >> 5;
    int wtask = blockIdx.x * 2 + wslot;   // 0..4863
    int lane = threadIdx.x & 31;
    int c = wtask >> 8;
    int d = wtask & 255;
    int off = g_off[c];
    int cnt = g_off[c + 1] - off;
    const float LOG2E = 1.4426950408889634f;

    if (cnt > 0) {
        const float* __restrict__ fp = g_Fs + d * NPIX + off;

        // pass 1: mean/var (also warms L1 for the KDE passes)
        float s1 = 0.f, s2 = 0.f;
        for (int i = lane; i < cnt; i += 32) {
            float f = fp[i];
            s1 += f;
            s2 = fmaf(f, f, s2);
        }
        s1 = wredsum(s1);
        s2 = wredsum(s2);
        float cm  = (float)cnt;
        float miu = s1 / cm;
        float var = fmaxf(s2 / cm - miu * miu, 1e-12f);

        // vs = var/25 ; base-2 coef: -12.5*log2e/var
        float a_s = -12.5f * LOG2E / var;

        if (var >= 0.6f) {
            float sg = ex2(0.08f * a_s);
            unsigned long long sg2 = pk2(sg, sg);
            kde_recp<17, 0>(fp, cnt, lane, a_s, sg2, &sh[wslot][0]);
            kde_recp<17, 17>(fp, cnt, lane, a_s, sg2, &sh[wslot][17]);
            kde_recp<17, 34>(fp, cnt, lane, a_s, sg2, &sh[wslot][34]);
        } else {
            kde_direct<24, 0>(fp, cnt, lane, a_s, &sh[wslot][0]);
            kde_direct<27, 24>(fp, cnt, lane, a_s, &sh[wslot][24]);
        }
        __syncwarp();

        // epilogue: lane k owns bins k and k+32
        bool hi = lane < (NBINS - 32);
        float sv0 = sh[wslot][lane];
        float sv1 = hi ? sh[wslot][lane + 32] : 0.f;
        float sumS = wredsum(sv0 + sv1);

        float at = -0.5f * LOG2E / var;
        float b0 = fmaf(0.2f, (float)lane, -5.f);
        float b1 = b0 + 6.4f;
        float d0 = b0 - miu, d1 = b1 - miu;
        float g0 = ex2(at * d0 * d0);
        float g1 = hi ? ex2(at * d1 * d1) : 0.f;
        float sumT = wredsum(g0 + g1);

        float invS = 1.f / fmaxf(sumS, 1e-30f);
        float invT = 1.f / fmaxf(sumT, 1e-30f);

        float df0 = sv0 * invS - g0 * invT;
        float df1 = sv1 * invS - g1 * invT;
        float ad0 = fabsf(df0), ad1 = fabsf(df1);
        float l0 = (ad0 < 1.f) ? 0.5f * df0 * df0 : ad0 - 0.5f;
        float l1 = (ad1 < 1.f) ? 0.5f * df1 * df1 : ad1 - 0.5f;
        if (!hi) l1 = 0.f;

        float sl = wredsum(l0 + l1);
        if (lane == 0) atomicAdd(&g_clsum2[c * 32 + (d & 31)], sl);
    }

    // publish, ticket; the last of the NW warps finalizes.
    __threadfence();
    int tk = 0;
    if (lane == 0) tk = atomicAdd(&g_ticket, 1);
    tk = __shfl_sync(0xffffffffu, tk, 0);
    if (tk == NW - 1) {
        float v = 0.f, a = 0.f;
#pragma unroll
        for (int j = 1; j < NCLS; j++) {          // class 0 excluded
            int cj = __ldcg(&g_cnt[j]);
            float x = __ldcg(&g_clsum2[j * 32 + lane]);
            if (cj > 0) { v += x; a += (lane == 0) ? 1.f : 0.f; }
        }
        v = wredsum(v);
        a = wredsum(a);
        if (lane == 0) out[0] = (v * (1.f / 13056.f)) / (a + 1e-12f);
    }

    // output copy: out[1..nf] = feature[0..nf), overlapped across blocks
    int gt = blockIdx.x * 64 + threadIdx.x;
    for (int j = gt; j < nf; j += NBLK * 64)
        out[1 + j] = feature[j];
}

extern "C" void kernel_launch(void* const* d_in, const int* in_sizes, int n_in,
                              void* d_out, int out_size) {
    // Inputs: feature (1048576 f32) and label (4096 px); smaller buffer = label.
    int fi = 0, li = 1;
    if (n_in >= 2 && in_sizes[0] < in_sizes[1]) { fi = 1; li = 0; }
    const float* feature = (const float*)d_in[fi];
    const int*   label   = (const int*)d_in[li];
    float* out = (float*)d_out;

    int nf = out_size - 1;
    int cap = DIM * NPIX;
    if (nf > cap) nf = cap;
    if (nf < 0) nf = 0;

    k_gp<<<128, 256>>>(label, feature);
    k_main<<<NBLK, 64>>>(feature, out, nf);
}